// round 6
// baseline (speedup 1.0000x reference)
#include <cuda_runtime.h>
#include <cstdint>
#include <cstddef>

// Problem dims
#define BB 2
#define MM 4096
#define NN 4096
#define KK 4096
#define NT (KK / 128)          // 32 K-tiles of 128 bytes

// Packed sign operands (s8 in {+1,-1}); static scratch (no allocs allowed).
__device__ __align__(16) signed char g_xi8[(size_t)BB * MM * KK];
__device__ __align__(16) signed char g_yi8[(size_t)BB * NN * KK];

// ---------------------------------------------------------------------------
// Pack: fp32 -> s8 sign (+1 / -1)
// ---------------------------------------------------------------------------
__global__ void pack_signs(const float* __restrict__ in, signed char* __restrict__ out, int n4) {
    int i = blockIdx.x * blockDim.x + threadIdx.x;
    if (i >= n4) return;
    float4 v = reinterpret_cast<const float4*>(in)[i];
    char4 c;
    c.x = (__float_as_uint(v.x) >> 31) ? (signed char)-1 : (signed char)1;
    c.y = (__float_as_uint(v.y) >> 31) ? (signed char)-1 : (signed char)1;
    c.z = (__float_as_uint(v.z) >> 31) ? (signed char)-1 : (signed char)1;
    c.w = (__float_as_uint(v.w) >> 31) ? (signed char)-1 : (signed char)1;
    reinterpret_cast<char4*>(out)[i] = c;
}

// ---------------------------------------------------------------------------
// IMMA GEMM (mma.sync m16n8k32 s8), cp.async 4-stage pipeline, 1 sync/K-tile.
// CTA tile 256x128 (M x N), 512 threads = 16 warps (4M x 4N), warp tile 64x32.
// smem/stage: A 256x128B (32KB) + B 128x128B (16KB) = 48KB; 4 stages = 192KB.
// ---------------------------------------------------------------------------
static constexpr int STAGES     = 4;
static constexpr int STAGE_SZ   = 48 * 1024;
static constexpr int SMEM_TOTAL = STAGES * STAGE_SZ;   // 196608

__device__ __forceinline__ void ldsm_x4(uint32_t addr, uint32_t& r0, uint32_t& r1,
                                        uint32_t& r2, uint32_t& r3) {
    asm volatile("ldmatrix.sync.aligned.m8n8.x4.shared.b16 {%0,%1,%2,%3}, [%4];"
                 : "=r"(r0), "=r"(r1), "=r"(r2), "=r"(r3) : "r"(addr));
}

__device__ __forceinline__ void mma_s8(int* c, const uint32_t* a, const uint32_t* b) {
    asm volatile(
        "mma.sync.aligned.m16n8k32.row.col.s32.s8.s8.s32 "
        "{%0,%1,%2,%3}, {%4,%5,%6,%7}, {%8,%9}, {%0,%1,%2,%3};"
        : "+r"(c[0]), "+r"(c[1]), "+r"(c[2]), "+r"(c[3])
        : "r"(a[0]), "r"(a[1]), "r"(a[2]), "r"(a[3]), "r"(b[0]), "r"(b[1]));
}

__device__ __forceinline__ void cp16(uint32_t dst, const void* src) {
    asm volatile("cp.async.cg.shared.global [%0], [%1], 16;" :: "r"(dst), "l"(src));
}

__global__ void __launch_bounds__(512, 1)
bingemm_imma(const float* __restrict__ xclip, const float* __restrict__ yclip,
             float* __restrict__ out) {
    extern __shared__ __align__(1024) char smem[];
    uint32_t sb;
    asm("{ .reg .u64 t; cvta.to.shared.u64 t, %1; cvt.u32.u64 %0, t; }" : "=r"(sb) : "l"(smem));

    const int tid  = threadIdx.x;
    const int lane = tid & 31;
    const int wid  = tid >> 5;
    const int wm   = wid >> 2;          // 0..3  (M warp, 64 rows each)
    const int wn   = wid & 3;           // 0..3  (N warp, 32 cols each)
    const int tn = blockIdx.x, tm = blockIdx.y, b = blockIdx.z;

    const signed char* Ab = g_xi8 + ((size_t)b * MM + (size_t)tm * 256) * KK;
    const signed char* Bb = g_yi8 + ((size_t)b * NN + (size_t)tn * 128) * KK;

    // ldmatrix per-lane coordinates (validated in R4)
    const int rowA_l = (lane & 15);
    const int hiA    = lane >> 4;
    const int rowB_l = (lane & 7) + ((lane >> 4) << 3);
    const int hiB    = (lane >> 3) & 1;

    int acc[4][4][4];                            // [mf][nf][reg]
    #pragma unroll
    for (int i = 0; i < 4; i++)
        #pragma unroll
        for (int j = 0; j < 4; j++)
            #pragma unroll
            for (int r = 0; r < 4; r++) acc[i][j][r] = 0;

    // --- stage loader: A 2048 vec (4/thread) + B 1024 vec (2/thread) ---
    auto load_stage = [&](int slot, int kt) {
        const uint32_t stA = sb + slot * STAGE_SZ;
        const uint32_t stB = stA + 32768;
        const int koff = kt * 128;
        #pragma unroll
        for (int i = 0; i < 4; i++) {
            int idx   = tid + i * 512;           // 0..2047
            int row   = idx >> 3;                // 0..255
            int chunk = idx & 7;
            uint32_t sw = (uint32_t)((chunk ^ (row & 7)) << 4);
            cp16(stA + row * 128 + sw, Ab + (size_t)row * KK + koff + chunk * 16);
        }
        #pragma unroll
        for (int i = 0; i < 2; i++) {
            int idx   = tid + i * 512;           // 0..1023
            int row   = idx >> 3;                // 0..127
            int chunk = idx & 7;
            uint32_t sw = (uint32_t)((chunk ^ (row & 7)) << 4);
            cp16(stB + row * 128 + sw, Bb + (size_t)row * KK + koff + chunk * 16);
        }
        asm volatile("cp.async.commit_group;" ::: "memory");
    };

    // prologue: tiles 0..STAGES-2
    #pragma unroll
    for (int t = 0; t < STAGES - 1; t++) load_stage(t, t);

    for (int kt = 0; kt < NT; kt++) {
        // Tile kt's group is complete once <= STAGES-2 groups remain pending
        // (exactly one group committed per iteration, empty ones at the tail).
        asm volatile("cp.async.wait_group %0;" :: "n"(STAGES - 2) : "memory");
        __syncthreads();   // also: all warps finished reading slot (kt-1)%S

        if (kt + STAGES - 1 < NT) load_stage((kt + STAGES - 1) % STAGES, kt + STAGES - 1);
        else asm volatile("cp.async.commit_group;" ::: "memory");

        const uint32_t stA = sb + (kt % STAGES) * STAGE_SZ;
        const uint32_t stB = stA + 32768;

        #pragma unroll
        for (int ks = 0; ks < 4; ks++) {
            uint32_t a[4][4];
            #pragma unroll
            for (int mf = 0; mf < 4; mf++) {
                int r = wm * 64 + mf * 16 + rowA_l;
                int c = (2 * ks + hiA) ^ (r & 7);
                ldsm_x4(stA + r * 128 + c * 16, a[mf][0], a[mf][1], a[mf][2], a[mf][3]);
            }
            uint32_t bfr[4][2];
            #pragma unroll
            for (int p = 0; p < 2; p++) {
                int r = wn * 32 + p * 16 + rowB_l;
                int c = (2 * ks + hiB) ^ (r & 7);
                ldsm_x4(stB + r * 128 + c * 16,
                        bfr[2 * p][0], bfr[2 * p][1], bfr[2 * p + 1][0], bfr[2 * p + 1][1]);
            }
            #pragma unroll
            for (int mf = 0; mf < 4; mf++)
                #pragma unroll
                for (int nf = 0; nf < 4; nf++)
                    mma_s8(acc[mf][nf], a[mf], bfr[nf]);
        }
    }

    // --- epilogue: registers -> gmem, scaled ---
    const float scale = xclip[0] * yclip[0];
    const int mbase = tm * 256 + wm * 64 + (lane >> 2);
    const int nbase = tn * 128 + wn * 32 + (lane & 3) * 2;

    #pragma unroll
    for (int mf = 0; mf < 4; mf++) {
        #pragma unroll
        for (int nf = 0; nf < 4; nf++) {
            int m0 = mbase + mf * 16;
            int n0 = nbase + nf * 8;
            float2 v0, v1;
            v0.x = (float)acc[mf][nf][0] * scale;
            v0.y = (float)acc[mf][nf][1] * scale;
            v1.x = (float)acc[mf][nf][2] * scale;
            v1.y = (float)acc[mf][nf][3] * scale;
            *reinterpret_cast<float2*>(out + ((size_t)b * MM + m0) * NN + n0)       = v0;
            *reinterpret_cast<float2*>(out + ((size_t)b * MM + m0 + 8) * NN + n0)   = v1;
        }
    }
}

// ---------------------------------------------------------------------------
// Launch
// ---------------------------------------------------------------------------
extern "C" void kernel_launch(void* const* d_in, const int* in_sizes, int n_in,
                              void* d_out, int out_size) {
    const float* x     = (const float*)d_in[0];
    const float* y     = (const float*)d_in[1];
    const float* xclip = (const float*)d_in[2];
    const float* yclip = (const float*)d_in[3];
    float* out = (float*)d_out;

    signed char *xi8, *yi8;
    cudaGetSymbolAddress((void**)&xi8, g_xi8);
    cudaGetSymbolAddress((void**)&yi8, g_yi8);

    int n4x = in_sizes[0] / 4;
    int n4y = in_sizes[1] / 4;
    pack_signs<<<(n4x + 255) / 256, 256>>>(x, xi8, n4x);
    pack_signs<<<(n4y + 255) / 256, 256>>>(y, yi8, n4y);

    cudaFuncSetAttribute(bingemm_imma, cudaFuncAttributeMaxDynamicSharedMemorySize, SMEM_TOTAL);
    dim3 grid(NN / 128, MM / 256, BB);
    bingemm_imma<<<grid, 512, SMEM_TOTAL>>>(xclip, yclip, out);
}

// round 7
// speedup vs baseline: 1.6714x; 1.6714x over previous
#include <cuda_runtime.h>
#include <cstdint>
#include <cstddef>

// Problem dims
#define BB 2
#define MM 4096
#define NN 4096
#define KK 4096
#define NT (KK / 128)          // 32 K-tiles of 128 bytes

// Packed sign operands, PRE-TILED + PRE-SWIZZLED:
// tile (b, t, kt) of [128 rows x 128 bytes] stored contiguously (16 KB),
// bytes within the tile at SW128-swizzled offsets.
__device__ __align__(16) signed char g_xi8[(size_t)BB * MM * KK];
__device__ __align__(16) signed char g_yi8[(size_t)BB * NN * KK];

// ---------------------------------------------------------------------------
// Pack: fp32 -> s8 sign (+1/-1), written into tiled+swizzled layout.
// Thread handles 4 consecutive k of one row (char4 stays inside a 16B unit,
// SW128 XOR only touches bits [4:7)).
// ---------------------------------------------------------------------------
__global__ void pack_signs_tiled(const float* __restrict__ in,
                                 signed char* __restrict__ out,
                                 int rows, int total4) {
    int i = blockIdx.x * blockDim.x + threadIdx.x;
    if (i >= total4) return;
    const int k4r = KK / 4;
    int k  = (i % k4r) * 4;
    int m  = (i / k4r) % rows;
    int b  = i / (k4r * rows);

    float4 v = reinterpret_cast<const float4*>(in)[i];
    char4 c;
    c.x = (__float_as_uint(v.x) >> 31) ? (signed char)-1 : (signed char)1;
    c.y = (__float_as_uint(v.y) >> 31) ? (signed char)-1 : (signed char)1;
    c.z = (__float_as_uint(v.z) >> 31) ? (signed char)-1 : (signed char)1;
    c.w = (__float_as_uint(v.w) >> 31) ? (signed char)-1 : (signed char)1;

    size_t tile = ((size_t)b * (rows / 128) + (m >> 7)) * (KK / 128) + (k >> 7);
    uint32_t off = (uint32_t)((m & 127) * 128 + (k & 127));
    uint32_t sw  = off ^ ((off >> 3) & 0x70);
    *reinterpret_cast<char4*>(out + tile * 16384 + sw) = c;
}

// ---------------------------------------------------------------------------
// IMMA GEMM: 128x128 CTA tile, 256 thr (2M x 4N warps, 64x32 warp tile),
// 3-stage bulk-TMA pipeline (cp.async.bulk + mbarrier complete_tx).
// smem: [0:24) 3 mbarriers | stages at 1024 + s*32768 (A 16K, B 16K).
// ---------------------------------------------------------------------------
static constexpr int STAGES     = 3;
static constexpr int STAGE_SZ   = 32 * 1024;
static constexpr int SMEM_TOTAL = 1024 + STAGES * STAGE_SZ;   // 99328

__device__ __forceinline__ void ldsm_x4(uint32_t addr, uint32_t& r0, uint32_t& r1,
                                        uint32_t& r2, uint32_t& r3) {
    asm volatile("ldmatrix.sync.aligned.m8n8.x4.shared.b16 {%0,%1,%2,%3}, [%4];"
                 : "=r"(r0), "=r"(r1), "=r"(r2), "=r"(r3) : "r"(addr));
}

__device__ __forceinline__ void mma_s8(int* c, const uint32_t* a, const uint32_t* b) {
    asm volatile(
        "mma.sync.aligned.m16n8k32.row.col.s32.s8.s8.s32 "
        "{%0,%1,%2,%3}, {%4,%5,%6,%7}, {%8,%9}, {%0,%1,%2,%3};"
        : "+r"(c[0]), "+r"(c[1]), "+r"(c[2]), "+r"(c[3])
        : "r"(a[0]), "r"(a[1]), "r"(a[2]), "r"(a[3]), "r"(b[0]), "r"(b[1]));
}

__global__ void __launch_bounds__(256, 2)
bingemm_imma(const float* __restrict__ xclip, const float* __restrict__ yclip,
             float* __restrict__ out) {
    extern __shared__ __align__(1024) char smem[];
    uint32_t sb;
    asm("{ .reg .u64 t; cvta.to.shared.u64 t, %1; cvt.u32.u64 %0, t; }" : "=r"(sb) : "l"(smem));

    const int tid  = threadIdx.x;
    const int lane = tid & 31;
    const int wid  = tid >> 5;
    const int wm   = wid >> 2;          // 0..1
    const int wn   = wid & 3;           // 0..3
    const int tn = blockIdx.x, tm = blockIdx.y, b = blockIdx.z;

    // Tiled operand bases: tile index = ((b*32 + trow)*32 + kt) * 16384
    const signed char* Abase = g_xi8 + (((size_t)b * 32 + tm) * 32) * 16384;
    const signed char* Bbase = g_yi8 + (((size_t)b * 32 + tn) * 32) * 16384;

    // mbarrier init
    if (tid == 0) {
        #pragma unroll
        for (int s = 0; s < STAGES; s++)
            asm volatile("mbarrier.init.shared.b64 [%0], %1;"
                         :: "r"(sb + s * 8), "r"(1u) : "memory");
    }
    __syncthreads();

    auto issue = [&](int kt, int slot) {
        uint32_t mbar = sb + slot * 8;
        uint32_t stA  = sb + 1024 + slot * STAGE_SZ;
        uint32_t stB  = stA + 16384;
        asm volatile("mbarrier.arrive.expect_tx.shared.b64 _, [%0], %1;"
                     :: "r"(mbar), "r"(32768u) : "memory");
        asm volatile("cp.async.bulk.shared::cta.global.mbarrier::complete_tx::bytes "
                     "[%0], [%1], %2, [%3];"
                     :: "r"(stA), "l"(Abase + (size_t)kt * 16384), "r"(16384u), "r"(mbar)
                     : "memory");
        asm volatile("cp.async.bulk.shared::cta.global.mbarrier::complete_tx::bytes "
                     "[%0], [%1], %2, [%3];"
                     :: "r"(stB), "l"(Bbase + (size_t)kt * 16384), "r"(16384u), "r"(mbar)
                     : "memory");
    };

    // prologue: tiles 0..2 into slots 0..2
    if (tid == 0) {
        #pragma unroll
        for (int t = 0; t < STAGES; t++) issue(t, t);
    }

    // ldmatrix per-lane coordinates (validated in R4)
    const int rowA_l = (lane & 15);
    const int hiA    = lane >> 4;
    const int rowB_l = (lane & 7) + ((lane >> 4) << 3);
    const int hiB    = (lane >> 3) & 1;

    int acc[4][4][4];
    #pragma unroll
    for (int i = 0; i < 4; i++)
        #pragma unroll
        for (int j = 0; j < 4; j++)
            #pragma unroll
            for (int r = 0; r < 4; r++) acc[i][j][r] = 0;

    for (int kt = 0; kt < NT; kt++) {
        const int slot = kt % STAGES;
        const uint32_t mbar  = sb + slot * 8;
        const uint32_t par   = (uint32_t)((kt / STAGES) & 1);

        // Wait for tile kt (acquire orders the async writes for ldmatrix).
        {
            uint32_t done;
            asm volatile(
                "{ .reg .pred p; mbarrier.try_wait.parity.acquire.cta.shared::cta.b64 p, [%1], %2;"
                " selp.b32 %0, 1, 0, p; }"
                : "=r"(done) : "r"(mbar), "r"(par) : "memory");
            if (!done) {
                asm volatile(
                    "{ .reg .pred P1;\n\t"
                    "WL%=: mbarrier.try_wait.parity.acquire.cta.shared::cta.b64 P1, [%0], %1, 0x989680;\n\t"
                    "@P1 bra.uni WD%=;\n\t"
                    "bra.uni WL%=;\n\t"
                    "WD%=: }"
                    :: "r"(mbar), "r"(par) : "memory");
            }
        }

        const uint32_t stA = sb + 1024 + slot * STAGE_SZ;
        const uint32_t stB = stA + 16384;

        #pragma unroll
        for (int ks = 0; ks < 4; ks++) {
            uint32_t a[4][4];
            #pragma unroll
            for (int mf = 0; mf < 4; mf++) {
                int r = wm * 64 + mf * 16 + rowA_l;
                int c = (2 * ks + hiA) ^ (r & 7);
                ldsm_x4(stA + r * 128 + c * 16, a[mf][0], a[mf][1], a[mf][2], a[mf][3]);
            }
            uint32_t bfr[4][2];
            #pragma unroll
            for (int p = 0; p < 2; p++) {
                int r = wn * 32 + p * 16 + rowB_l;
                int c = (2 * ks + hiB) ^ (r & 7);
                ldsm_x4(stB + r * 128 + c * 16,
                        bfr[2 * p][0], bfr[2 * p][1], bfr[2 * p + 1][0], bfr[2 * p + 1][1]);
            }
            #pragma unroll
            for (int mf = 0; mf < 4; mf++)
                #pragma unroll
                for (int nf = 0; nf < 4; nf++)
                    mma_s8(acc[mf][nf], a[mf], bfr[nf]);
        }

        // All warps done reading slot -> safe to refill with tile kt+3.
        __syncthreads();
        if (tid == 0 && kt + STAGES < NT) issue(kt + STAGES, slot);
    }

    // --- epilogue: registers -> gmem, scaled ---
    const float scale = xclip[0] * yclip[0];
    const int mbase = tm * 128 + wm * 64 + (lane >> 2);
    const int nbase = tn * 128 + wn * 32 + (lane & 3) * 2;

    #pragma unroll
    for (int mf = 0; mf < 4; mf++) {
        #pragma unroll
        for (int nf = 0; nf < 4; nf++) {
            int m0 = mbase + mf * 16;
            int n0 = nbase + nf * 8;
            float2 v0, v1;
            v0.x = (float)acc[mf][nf][0] * scale;
            v0.y = (float)acc[mf][nf][1] * scale;
            v1.x = (float)acc[mf][nf][2] * scale;
            v1.y = (float)acc[mf][nf][3] * scale;
            *reinterpret_cast<float2*>(out + ((size_t)b * MM + m0) * NN + n0)       = v0;
            *reinterpret_cast<float2*>(out + ((size_t)b * MM + m0 + 8) * NN + n0)   = v1;
        }
    }

    __syncthreads();
    if (tid == 0) {
        #pragma unroll
        for (int s = 0; s < STAGES; s++)
            asm volatile("mbarrier.inval.shared.b64 [%0];" :: "r"(sb + s * 8) : "memory");
    }
}

// ---------------------------------------------------------------------------
// Launch
// ---------------------------------------------------------------------------
extern "C" void kernel_launch(void* const* d_in, const int* in_sizes, int n_in,
                              void* d_out, int out_size) {
    const float* x     = (const float*)d_in[0];
    const float* y     = (const float*)d_in[1];
    const float* xclip = (const float*)d_in[2];
    const float* yclip = (const float*)d_in[3];
    float* out = (float*)d_out;

    signed char *xi8, *yi8;
    cudaGetSymbolAddress((void**)&xi8, g_xi8);
    cudaGetSymbolAddress((void**)&yi8, g_yi8);

    int n4x = in_sizes[0] / 4;
    int n4y = in_sizes[1] / 4;
    pack_signs_tiled<<<(n4x + 255) / 256, 256>>>(x, xi8, MM, n4x);
    pack_signs_tiled<<<(n4y + 255) / 256, 256>>>(y, yi8, NN, n4y);

    cudaFuncSetAttribute(bingemm_imma, cudaFuncAttributeMaxDynamicSharedMemorySize, SMEM_TOTAL);
    dim3 grid(NN / 128, MM / 128, BB);
    bingemm_imma<<<grid, 256, SMEM_TOTAL>>>(xclip, yclip, out);
}

// round 8
// speedup vs baseline: 2.7226x; 1.6289x over previous
#include <cuda_runtime.h>
#include <cstdint>
#include <cstddef>

// Problem dims
#define BB 2
#define MM 4096
#define NN 4096
#define KK 4096
#define KW 128              // 4096 bits = 128 u32 words per row
#define KW_CHUNK 64         // K processed in 2 chunks of 64 words

// Bit-packed signs, TRANSPOSED: word(b, kw, m) at [b][kw][m].
// bit l of word (kw) = sign bit of element k = kw*32 + l.
__device__ __align__(16) uint32_t g_xb[(size_t)BB * KW * MM];   // 4 MB
__device__ __align__(16) uint32_t g_yb[(size_t)BB * KW * NN];   // 4 MB

// ---------------------------------------------------------------------------
// Pack: fp32 -> 1-bit sign via warp ballot, transposed write [b][kw][m].
// One warp produces one u32 word (reads 128B coalesced).
// ---------------------------------------------------------------------------
__global__ void pack_bits(const float* __restrict__ in, uint32_t* __restrict__ out,
                          int rows, int nwords) {
    int t    = blockIdx.x * blockDim.x + threadIdx.x;
    int gw   = t >> 5;
    int lane = t & 31;
    if (gw >= nwords) return;
    int m  = gw % rows;
    int kw = (gw / rows) % KW;
    int b  = gw / (rows * KW);
    float v = in[((size_t)b * rows + m) * KK + kw * 32 + lane];
    unsigned mask = __ballot_sync(0xFFFFFFFFu, (__float_as_uint(v) >> 31) != 0u);
    if (lane == 0) out[((size_t)b * KW + kw) * rows + m] = mask;
}

// ---------------------------------------------------------------------------
// POPC GEMM: dot(m,n) = KK - 2 * sum_kw popc(x[m] ^ y[n]).
// CTA tile 128x128 outputs, 256 threads, 8x8 outputs/thread.
// smem: As[64][128] u32 + Bs[64][128] u32 = 64 KB (kw-major rows).
// ---------------------------------------------------------------------------
static constexpr int SMEM_TOTAL = 2 * KW_CHUNK * 128 * 4;   // 65536

__device__ __forceinline__ void cp16(uint32_t dst, const void* src) {
    asm volatile("cp.async.cg.shared.global [%0], [%1], 16;" :: "r"(dst), "l"(src));
}

__global__ void __launch_bounds__(256, 2)
bingemm_popc(const float* __restrict__ xclip, const float* __restrict__ yclip,
             float* __restrict__ out) {
    extern __shared__ __align__(16) uint32_t smem[];
    uint32_t* As = smem;                    // [kw][m]  64 x 128
    uint32_t* Bs = smem + KW_CHUNK * 128;   // [kw][n]  64 x 128
    uint32_t sb;
    asm("{ .reg .u64 t; cvta.to.shared.u64 t, %1; cvt.u32.u64 %0, t; }" : "=r"(sb) : "l"(smem));
    const uint32_t sbB = sb + KW_CHUNK * 128 * 4;

    const int tid = threadIdx.x;
    const int tm8 = tid >> 4;     // 0..15 -> 8 m-rows
    const int tn8 = tid & 15;     // 0..15 -> 8 n-cols
    const int tn = blockIdx.x, tm = blockIdx.y, b = blockIdx.z;

    const uint32_t* Ag = g_xb + (size_t)b * KW * MM + (size_t)tm * 128;
    const uint32_t* Bg = g_yb + (size_t)b * KW * NN + (size_t)tn * 128;

    int acc[8][8];
    #pragma unroll
    for (int i = 0; i < 8; i++)
        #pragma unroll
        for (int j = 0; j < 8; j++) acc[i][j] = 0;

    #pragma unroll 1
    for (int ck = 0; ck < KK / (KW_CHUNK * 32); ck++) {     // 2 chunks
        // --- load chunk: 64 rows x 512B per operand; 8 uint4/thread each ---
        #pragma unroll
        for (int v = 0; v < 8; v++) {
            int idx = tid + v * 256;        // 0..2047
            int row = idx >> 5;             // kw within chunk, 0..63
            int c4  = (idx & 31) * 4;       // word offset within row
            cp16(sb  + (row * 128 + c4) * 4, Ag + (size_t)(ck * KW_CHUNK + row) * MM + c4);
            cp16(sbB + (row * 128 + c4) * 4, Bg + (size_t)(ck * KW_CHUNK + row) * NN + c4);
        }
        asm volatile("cp.async.commit_group;" ::: "memory");
        asm volatile("cp.async.wait_group 0;" ::: "memory");
        __syncthreads();

        // --- compute: 64 kw, processed in pairs (POPC,POPC,IADD3) ---
        #pragma unroll 2
        for (int kw = 0; kw < KW_CHUNK; kw += 2) {
            uint4 a0 = *reinterpret_cast<const uint4*>(&As[kw * 128 + tm8 * 8]);
            uint4 a1 = *reinterpret_cast<const uint4*>(&As[kw * 128 + tm8 * 8 + 4]);
            uint4 a2 = *reinterpret_cast<const uint4*>(&As[(kw + 1) * 128 + tm8 * 8]);
            uint4 a3 = *reinterpret_cast<const uint4*>(&As[(kw + 1) * 128 + tm8 * 8 + 4]);
            uint4 b0 = *reinterpret_cast<const uint4*>(&Bs[kw * 128 + tn8 * 8]);
            uint4 b1 = *reinterpret_cast<const uint4*>(&Bs[kw * 128 + tn8 * 8 + 4]);
            uint4 b2 = *reinterpret_cast<const uint4*>(&Bs[(kw + 1) * 128 + tn8 * 8]);
            uint4 b3 = *reinterpret_cast<const uint4*>(&Bs[(kw + 1) * 128 + tn8 * 8 + 4]);
            uint32_t av[8]  = {a0.x, a0.y, a0.z, a0.w, a1.x, a1.y, a1.z, a1.w};
            uint32_t av2[8] = {a2.x, a2.y, a2.z, a2.w, a3.x, a3.y, a3.z, a3.w};
            uint32_t bv[8]  = {b0.x, b0.y, b0.z, b0.w, b1.x, b1.y, b1.z, b1.w};
            uint32_t bv2[8] = {b2.x, b2.y, b2.z, b2.w, b3.x, b3.y, b3.z, b3.w};
            #pragma unroll
            for (int i = 0; i < 8; i++)
                #pragma unroll
                for (int j = 0; j < 8; j++)
                    acc[i][j] += __popc(av[i] ^ bv[j]) + __popc(av2[i] ^ bv2[j]);
        }
        __syncthreads();   // before next chunk overwrites smem
    }

    // --- epilogue: dot = KK - 2*acc; scaled fp32 stores (2x float4 per row) ---
    const float scale = xclip[0] * yclip[0];
    const int m0 = tm * 128 + tm8 * 8;
    const int n0 = tn * 128 + tn8 * 8;

    #pragma unroll
    for (int i = 0; i < 8; i++) {
        float* orow = out + ((size_t)b * MM + m0 + i) * NN + n0;
        float4 v0, v1;
        v0.x = (float)(KK - 2 * acc[i][0]) * scale;
        v0.y = (float)(KK - 2 * acc[i][1]) * scale;
        v0.z = (float)(KK - 2 * acc[i][2]) * scale;
        v0.w = (float)(KK - 2 * acc[i][3]) * scale;
        v1.x = (float)(KK - 2 * acc[i][4]) * scale;
        v1.y = (float)(KK - 2 * acc[i][5]) * scale;
        v1.z = (float)(KK - 2 * acc[i][6]) * scale;
        v1.w = (float)(KK - 2 * acc[i][7]) * scale;
        *reinterpret_cast<float4*>(orow)     = v0;
        *reinterpret_cast<float4*>(orow + 4) = v1;
    }
}

// ---------------------------------------------------------------------------
// Launch
// ---------------------------------------------------------------------------
extern "C" void kernel_launch(void* const* d_in, const int* in_sizes, int n_in,
                              void* d_out, int out_size) {
    const float* x     = (const float*)d_in[0];
    const float* y     = (const float*)d_in[1];
    const float* xclip = (const float*)d_in[2];
    const float* yclip = (const float*)d_in[3];
    float* out = (float*)d_out;

    uint32_t *xb, *yb;
    cudaGetSymbolAddress((void**)&xb, g_xb);
    cudaGetSymbolAddress((void**)&yb, g_yb);

    const int nwords = BB * KW * MM;                    // 1,048,576 per tensor
    const int nthr   = nwords * 32;
    pack_bits<<<(nthr + 255) / 256, 256>>>(x, xb, MM, nwords);
    pack_bits<<<(nthr + 255) / 256, 256>>>(y, yb, NN, nwords);

    cudaFuncSetAttribute(bingemm_popc, cudaFuncAttributeMaxDynamicSharedMemorySize, SMEM_TOTAL);
    dim3 grid(NN / 128, MM / 128, BB);
    bingemm_popc<<<grid, 256, SMEM_TOTAL>>>(xclip, yclip, out);
}

// round 9
// speedup vs baseline: 3.2125x; 1.1800x over previous
#include <cuda_runtime.h>
#include <cstdint>
#include <cstddef>

// Problem dims
#define BB 2
#define MM 4096
#define NN 4096
#define KK 4096
#define KW 128              // 4096 bits = 128 u32 words per row
#define KW_CHUNK 64         // K processed in 2 chunks of 64 words

// Bit-packed signs, TRANSPOSED: word(b, kw, m) at [b][kw][m].
// bit l of word (kw) = sign bit of element k = kw*32 + l.
__device__ __align__(16) uint32_t g_xb[(size_t)BB * KW * MM];   // 4 MB
__device__ __align__(16) uint32_t g_yb[(size_t)BB * KW * NN];   // 4 MB

// ---------------------------------------------------------------------------
// Pack: fp32 -> 1-bit sign. ONE thread per output word: reads 32 consecutive
// floats (8 x float4, 128B contiguous), builds word, coalesced store.
// tid -> m fastest so stores to [b][kw][m] coalesce across the warp.
// ---------------------------------------------------------------------------
__global__ void pack_bits(const float* __restrict__ in, uint32_t* __restrict__ out,
                          int rows, int nwords) {
    int t = blockIdx.x * blockDim.x + threadIdx.x;
    if (t >= nwords) return;
    int m  = t % rows;
    int kw = (t / rows) % KW;
    int b  = t / (rows * KW);

    const float4* p = reinterpret_cast<const float4*>(
        in + ((size_t)b * rows + m) * KK + kw * 32);

    uint32_t w = 0;
    #pragma unroll
    for (int j = 0; j < 8; j++) {
        float4 v = p[j];
        w |= (__float_as_uint(v.x) >> 31) << (j * 4 + 0);
        w |= (__float_as_uint(v.y) >> 31) << (j * 4 + 1);
        w |= (__float_as_uint(v.z) >> 31) << (j * 4 + 2);
        w |= (__float_as_uint(v.w) >> 31) << (j * 4 + 3);
    }
    out[((size_t)b * KW + kw) * rows + m] = w;
}

// ---------------------------------------------------------------------------
// POPC GEMM: dot(m,n) = KK - 2 * sum_kw popc(x[m] ^ y[n]).
// CTA tile 128x128 outputs, 256 threads, 8x8 outputs/thread.
// smem: As[64][128] u32 + Bs[64][128] u32 = 64 KB (kw-major rows).
// (unchanged from R8 — controlled experiment)
// ---------------------------------------------------------------------------
static constexpr int SMEM_TOTAL = 2 * KW_CHUNK * 128 * 4;   // 65536

__device__ __forceinline__ void cp16(uint32_t dst, const void* src) {
    asm volatile("cp.async.cg.shared.global [%0], [%1], 16;" :: "r"(dst), "l"(src));
}

__global__ void __launch_bounds__(256, 2)
bingemm_popc(const float* __restrict__ xclip, const float* __restrict__ yclip,
             float* __restrict__ out) {
    extern __shared__ __align__(16) uint32_t smem[];
    uint32_t* As = smem;                    // [kw][m]  64 x 128
    uint32_t* Bs = smem + KW_CHUNK * 128;   // [kw][n]  64 x 128
    uint32_t sb;
    asm("{ .reg .u64 t; cvta.to.shared.u64 t, %1; cvt.u32.u64 %0, t; }" : "=r"(sb) : "l"(smem));
    const uint32_t sbB = sb + KW_CHUNK * 128 * 4;

    const int tid = threadIdx.x;
    const int tm8 = tid >> 4;     // 0..15 -> 8 m-rows
    const int tn8 = tid & 15;     // 0..15 -> 8 n-cols
    const int tn = blockIdx.x, tm = blockIdx.y, b = blockIdx.z;

    const uint32_t* Ag = g_xb + (size_t)b * KW * MM + (size_t)tm * 128;
    const uint32_t* Bg = g_yb + (size_t)b * KW * NN + (size_t)tn * 128;

    int acc[8][8];
    #pragma unroll
    for (int i = 0; i < 8; i++)
        #pragma unroll
        for (int j = 0; j < 8; j++) acc[i][j] = 0;

    #pragma unroll 1
    for (int ck = 0; ck < KK / (KW_CHUNK * 32); ck++) {     // 2 chunks
        // --- load chunk: 64 rows x 512B per operand; 8 uint4/thread each ---
        #pragma unroll
        for (int v = 0; v < 8; v++) {
            int idx = tid + v * 256;        // 0..2047
            int row = idx >> 5;             // kw within chunk, 0..63
            int c4  = (idx & 31) * 4;       // word offset within row
            cp16(sb  + (row * 128 + c4) * 4, Ag + (size_t)(ck * KW_CHUNK + row) * MM + c4);
            cp16(sbB + (row * 128 + c4) * 4, Bg + (size_t)(ck * KW_CHUNK + row) * NN + c4);
        }
        asm volatile("cp.async.commit_group;" ::: "memory");
        asm volatile("cp.async.wait_group 0;" ::: "memory");
        __syncthreads();

        // --- compute: 64 kw, processed in pairs (POPC,POPC,IADD3) ---
        #pragma unroll 2
        for (int kw = 0; kw < KW_CHUNK; kw += 2) {
            uint4 a0 = *reinterpret_cast<const uint4*>(&As[kw * 128 + tm8 * 8]);
            uint4 a1 = *reinterpret_cast<const uint4*>(&As[kw * 128 + tm8 * 8 + 4]);
            uint4 a2 = *reinterpret_cast<const uint4*>(&As[(kw + 1) * 128 + tm8 * 8]);
            uint4 a3 = *reinterpret_cast<const uint4*>(&As[(kw + 1) * 128 + tm8 * 8 + 4]);
            uint4 b0 = *reinterpret_cast<const uint4*>(&Bs[kw * 128 + tn8 * 8]);
            uint4 b1 = *reinterpret_cast<const uint4*>(&Bs[kw * 128 + tn8 * 8 + 4]);
            uint4 b2 = *reinterpret_cast<const uint4*>(&Bs[(kw + 1) * 128 + tn8 * 8]);
            uint4 b3 = *reinterpret_cast<const uint4*>(&Bs[(kw + 1) * 128 + tn8 * 8 + 4]);
            uint32_t av[8]  = {a0.x, a0.y, a0.z, a0.w, a1.x, a1.y, a1.z, a1.w};
            uint32_t av2[8] = {a2.x, a2.y, a2.z, a2.w, a3.x, a3.y, a3.z, a3.w};
            uint32_t bv[8]  = {b0.x, b0.y, b0.z, b0.w, b1.x, b1.y, b1.z, b1.w};
            uint32_t bv2[8] = {b2.x, b2.y, b2.z, b2.w, b3.x, b3.y, b3.z, b3.w};
            #pragma unroll
            for (int i = 0; i < 8; i++)
                #pragma unroll
                for (int j = 0; j < 8; j++)
                    acc[i][j] += __popc(av[i] ^ bv[j]) + __popc(av2[i] ^ bv2[j]);
        }
        __syncthreads();   // before next chunk overwrites smem
    }

    // --- epilogue: dot = KK - 2*acc; scaled fp32 stores (2x float4 per row) ---
    const float scale = xclip[0] * yclip[0];
    const int m0 = tm * 128 + tm8 * 8;
    const int n0 = tn * 128 + tn8 * 8;

    #pragma unroll
    for (int i = 0; i < 8; i++) {
        float* orow = out + ((size_t)b * MM + m0 + i) * NN + n0;
        float4 v0, v1;
        v0.x = (float)(KK - 2 * acc[i][0]) * scale;
        v0.y = (float)(KK - 2 * acc[i][1]) * scale;
        v0.z = (float)(KK - 2 * acc[i][2]) * scale;
        v0.w = (float)(KK - 2 * acc[i][3]) * scale;
        v1.x = (float)(KK - 2 * acc[i][4]) * scale;
        v1.y = (float)(KK - 2 * acc[i][5]) * scale;
        v1.z = (float)(KK - 2 * acc[i][6]) * scale;
        v1.w = (float)(KK - 2 * acc[i][7]) * scale;
        *reinterpret_cast<float4*>(orow)     = v0;
        *reinterpret_cast<float4*>(orow + 4) = v1;
    }
}

// ---------------------------------------------------------------------------
// Launch
// ---------------------------------------------------------------------------
extern "C" void kernel_launch(void* const* d_in, const int* in_sizes, int n_in,
                              void* d_out, int out_size) {
    const float* x     = (const float*)d_in[0];
    const float* y     = (const float*)d_in[1];
    const float* xclip = (const float*)d_in[2];
    const float* yclip = (const float*)d_in[3];
    float* out = (float*)d_out;

    uint32_t *xb, *yb;
    cudaGetSymbolAddress((void**)&xb, g_xb);
    cudaGetSymbolAddress((void**)&yb, g_yb);

    const int nwords = BB * KW * MM;                    // 1,048,576 per tensor
    pack_bits<<<(nwords + 255) / 256, 256>>>(x, xb, MM, nwords);
    pack_bits<<<(nwords + 255) / 256, 256>>>(y, yb, NN, nwords);

    cudaFuncSetAttribute(bingemm_popc, cudaFuncAttributeMaxDynamicSharedMemorySize, SMEM_TOTAL);
    dim3 grid(NN / 128, MM / 128, BB);
    bingemm_popc<<<grid, 256, SMEM_TOTAL>>>(xclip, yclip, out);
}

// round 10
// speedup vs baseline: 4.3959x; 1.3684x over previous
#include <cuda_runtime.h>
#include <cstdint>
#include <cstddef>

// Problem dims
#define BB 2
#define MM 4096
#define NN 4096
#define KK 4096
#define KW 128              // 4096 bits = 128 u32 words per row
#define KW_CHUNK 64         // K processed in 2 chunks of 64 words

// Bit-packed signs, TRANSPOSED: word(b, kw, m) at [b][kw][m].
__device__ __align__(16) uint32_t g_xb[(size_t)BB * KW * MM];   // 4 MB
__device__ __align__(16) uint32_t g_yb[(size_t)BB * KW * NN];   // 4 MB

// ---------------------------------------------------------------------------
// Pack: fp32 -> 1-bit sign. One thread per word (R9-validated).
// ---------------------------------------------------------------------------
__global__ void pack_bits(const float* __restrict__ in, uint32_t* __restrict__ out,
                          int rows, int nwords) {
    int t = blockIdx.x * blockDim.x + threadIdx.x;
    if (t >= nwords) return;
    int m  = t % rows;
    int kw = (t / rows) % KW;
    int b  = t / (rows * KW);

    const float4* p = reinterpret_cast<const float4*>(
        in + ((size_t)b * rows + m) * KK + kw * 32);

    uint32_t w = 0;
    #pragma unroll
    for (int j = 0; j < 8; j++) {
        float4 v = p[j];
        w |= (__float_as_uint(v.x) >> 31) << (j * 4 + 0);
        w |= (__float_as_uint(v.y) >> 31) << (j * 4 + 1);
        w |= (__float_as_uint(v.z) >> 31) << (j * 4 + 2);
        w |= (__float_as_uint(v.w) >> 31) << (j * 4 + 3);
    }
    out[((size_t)b * KW + kw) * rows + m] = w;
}

// ---------------------------------------------------------------------------
// POPC GEMM with 3:2 carry-save compression:
//   popc(x0)+popc(x1)+popc(x2) = popc(x0^x1^x2) + 2*popc(maj(x0,x1,x2))
// CTA tile 128x128 outputs, 256 threads, 8x8 outputs/thread.
// K chunk of 64 words processed as 21 groups of 3 + 1 leftover.
// ---------------------------------------------------------------------------
static constexpr int SMEM_TOTAL = 2 * KW_CHUNK * 128 * 4;   // 65536

__device__ __forceinline__ void cp16(uint32_t dst, const void* src) {
    asm volatile("cp.async.cg.shared.global [%0], [%1], 16;" :: "r"(dst), "l"(src));
}

__device__ __forceinline__ uint32_t maj3(uint32_t a, uint32_t b, uint32_t c) {
    uint32_t r;
    asm("lop3.b32 %0, %1, %2, %3, 0xE8;" : "=r"(r) : "r"(a), "r"(b), "r"(c));
    return r;
}
__device__ __forceinline__ uint32_t xor3(uint32_t a, uint32_t b, uint32_t c) {
    uint32_t r;
    asm("lop3.b32 %0, %1, %2, %3, 0x96;" : "=r"(r) : "r"(a), "r"(b), "r"(c));
    return r;
}

__global__ void __launch_bounds__(256, 2)
bingemm_popc(const float* __restrict__ xclip, const float* __restrict__ yclip,
             float* __restrict__ out) {
    extern __shared__ __align__(16) uint32_t smem[];
    uint32_t* As = smem;                    // [kw][m]  64 x 128
    uint32_t* Bs = smem + KW_CHUNK * 128;   // [kw][n]  64 x 128
    uint32_t sb;
    asm("{ .reg .u64 t; cvta.to.shared.u64 t, %1; cvt.u32.u64 %0, t; }" : "=r"(sb) : "l"(smem));
    const uint32_t sbB = sb + KW_CHUNK * 128 * 4;

    const int tid = threadIdx.x;
    const int tm8 = tid >> 4;     // 0..15 -> 8 m-rows
    const int tn8 = tid & 15;     // 0..15 -> 8 n-cols
    const int tn = blockIdx.x, tm = blockIdx.y, b = blockIdx.z;

    const uint32_t* Ag = g_xb + (size_t)b * KW * MM + (size_t)tm * 128;
    const uint32_t* Bg = g_yb + (size_t)b * KW * NN + (size_t)tn * 128;

    int acc[8][8];
    #pragma unroll
    for (int i = 0; i < 8; i++)
        #pragma unroll
        for (int j = 0; j < 8; j++) acc[i][j] = 0;

    #pragma unroll 1
    for (int ck = 0; ck < KK / (KW_CHUNK * 32); ck++) {     // 2 chunks
        // --- load chunk: 64 rows x 512B per operand; 8 uint4/thread each ---
        #pragma unroll
        for (int v = 0; v < 8; v++) {
            int idx = tid + v * 256;        // 0..2047
            int row = idx >> 5;             // kw within chunk, 0..63
            int c4  = (idx & 31) * 4;       // word offset within row
            cp16(sb  + (row * 128 + c4) * 4, Ag + (size_t)(ck * KW_CHUNK + row) * MM + c4);
            cp16(sbB + (row * 128 + c4) * 4, Bg + (size_t)(ck * KW_CHUNK + row) * NN + c4);
        }
        asm volatile("cp.async.commit_group;" ::: "memory");
        asm volatile("cp.async.wait_group 0;" ::: "memory");
        __syncthreads();

        // --- compute: 21 groups of 3 kw + 1 leftover (64 = 3*21 + 1) ---
        #pragma unroll 1
        for (int g = 0; g < 21; g++) {
            const int kw = g * 3;
            // A operand: 3 rows x 8 m-words (broadcast across 16 lanes)
            uint4 a00 = *reinterpret_cast<const uint4*>(&As[kw * 128 + tm8 * 8]);
            uint4 a01 = *reinterpret_cast<const uint4*>(&As[kw * 128 + tm8 * 8 + 4]);
            uint4 a10 = *reinterpret_cast<const uint4*>(&As[(kw + 1) * 128 + tm8 * 8]);
            uint4 a11 = *reinterpret_cast<const uint4*>(&As[(kw + 1) * 128 + tm8 * 8 + 4]);
            uint4 a20 = *reinterpret_cast<const uint4*>(&As[(kw + 2) * 128 + tm8 * 8]);
            uint4 a21 = *reinterpret_cast<const uint4*>(&As[(kw + 2) * 128 + tm8 * 8 + 4]);
            uint32_t av0[8] = {a00.x, a00.y, a00.z, a00.w, a01.x, a01.y, a01.z, a01.w};
            uint32_t av1[8] = {a10.x, a10.y, a10.z, a10.w, a11.x, a11.y, a11.z, a11.w};
            uint32_t av2[8] = {a20.x, a20.y, a20.z, a20.w, a21.x, a21.y, a21.z, a21.w};

            // B in two halves of 4 n-words to cap register pressure
            #pragma unroll
            for (int h = 0; h < 2; h++) {
                uint4 b0 = *reinterpret_cast<const uint4*>(&Bs[kw * 128 + tn8 * 8 + h * 4]);
                uint4 b1 = *reinterpret_cast<const uint4*>(&Bs[(kw + 1) * 128 + tn8 * 8 + h * 4]);
                uint4 b2 = *reinterpret_cast<const uint4*>(&Bs[(kw + 2) * 128 + tn8 * 8 + h * 4]);
                uint32_t bv0[4] = {b0.x, b0.y, b0.z, b0.w};
                uint32_t bv1[4] = {b1.x, b1.y, b1.z, b1.w};
                uint32_t bv2[4] = {b2.x, b2.y, b2.z, b2.w};
                #pragma unroll
                for (int i = 0; i < 8; i++) {
                    #pragma unroll
                    for (int j = 0; j < 4; j++) {
                        uint32_t x0 = av0[i] ^ bv0[j];
                        uint32_t x1 = av1[i] ^ bv1[j];
                        uint32_t x2 = av2[i] ^ bv2[j];
                        uint32_t s  = xor3(x0, x1, x2);
                        uint32_t c  = maj3(x0, x1, x2);
                        acc[i][h * 4 + j] += __popc(s) + 2 * __popc(c);
                    }
                }
            }
        }
        // leftover kw = 63
        {
            const int kw = 63;
            uint4 a0 = *reinterpret_cast<const uint4*>(&As[kw * 128 + tm8 * 8]);
            uint4 a1 = *reinterpret_cast<const uint4*>(&As[kw * 128 + tm8 * 8 + 4]);
            uint4 b0 = *reinterpret_cast<const uint4*>(&Bs[kw * 128 + tn8 * 8]);
            uint4 b1 = *reinterpret_cast<const uint4*>(&Bs[kw * 128 + tn8 * 8 + 4]);
            uint32_t av[8] = {a0.x, a0.y, a0.z, a0.w, a1.x, a1.y, a1.z, a1.w};
            uint32_t bv[8] = {b0.x, b0.y, b0.z, b0.w, b1.x, b1.y, b1.z, b1.w};
            #pragma unroll
            for (int i = 0; i < 8; i++)
                #pragma unroll
                for (int j = 0; j < 8; j++)
                    acc[i][j] += __popc(av[i] ^ bv[j]);
        }
        __syncthreads();   // before next chunk overwrites smem
    }

    // --- epilogue: dot = KK - 2*acc; scaled fp32 stores ---
    const float scale = xclip[0] * yclip[0];
    const int m0 = tm * 128 + tm8 * 8;
    const int n0 = tn * 128 + tn8 * 8;

    #pragma unroll
    for (int i = 0; i < 8; i++) {
        float* orow = out + ((size_t)b * MM + m0 + i) * NN + n0;
        float4 v0, v1;
        v0.x = (float)(KK - 2 * acc[i][0]) * scale;
        v0.y = (float)(KK - 2 * acc[i][1]) * scale;
        v0.z = (float)(KK - 2 * acc[i][2]) * scale;
        v0.w = (float)(KK - 2 * acc[i][3]) * scale;
        v1.x = (float)(KK - 2 * acc[i][4]) * scale;
        v1.y = (float)(KK - 2 * acc[i][5]) * scale;
        v1.z = (float)(KK - 2 * acc[i][6]) * scale;
        v1.w = (float)(KK - 2 * acc[i][7]) * scale;
        *reinterpret_cast<float4*>(orow)     = v0;
        *reinterpret_cast<float4*>(orow + 4) = v1;
    }
}

// ---------------------------------------------------------------------------
// Launch
// ---------------------------------------------------------------------------
extern "C" void kernel_launch(void* const* d_in, const int* in_sizes, int n_in,
                              void* d_out, int out_size) {
    const float* x     = (const float*)d_in[0];
    const float* y     = (const float*)d_in[1];
    const float* xclip = (const float*)d_in[2];
    const float* yclip = (const float*)d_in[3];
    float* out = (float*)d_out;

    uint32_t *xb, *yb;
    cudaGetSymbolAddress((void**)&xb, g_xb);
    cudaGetSymbolAddress((void**)&yb, g_yb);

    const int nwords = BB * KW * MM;                    // 1,048,576 per tensor
    pack_bits<<<(nwords + 255) / 256, 256>>>(x, xb, MM, nwords);
    pack_bits<<<(nwords + 255) / 256, 256>>>(y, yb, NN, nwords);

    cudaFuncSetAttribute(bingemm_popc, cudaFuncAttributeMaxDynamicSharedMemorySize, SMEM_TOTAL);
    dim3 grid(NN / 128, MM / 128, BB);
    bingemm_popc<<<grid, 256, SMEM_TOTAL>>>(xclip, yclip, out);
}